// round 1
// baseline (speedup 1.0000x reference)
#include <cuda_runtime.h>
#include <cuda_bf16.h>

// Sinkhorn OT loss: B=1024 batches, N=M=256, 100 iterations, eps=0.1.
// One CTA per batch. K = exp(-C/eps) stored in SMEM as bf16 (padded rows),
// iterations done with packed fp32x2 FMAs, fp32 accumulation.

#define BATCH   1024
#define NDIM    256
#define ROWPAD  264            // halves per row (8-half pad: 528B stride, conflict-free)
#define ITERS   100
#define NTHREADS 512

#define KS_BYTES   (NDIM * ROWPAD * 2)           // 135168
#define PART_OFF   (KS_BYTES)                    // float part[16*256]
#define PART_FLOATS 4096
#define SMEM_BYTES (KS_BYTES + (PART_FLOATS + 256*4 + 512 + 32) * 4)

__device__ float g_cost[BATCH];

// ---- packed f32x2 helpers -------------------------------------------------
__device__ __forceinline__ unsigned long long pk2(float lo, float hi) {
    unsigned long long r;
    asm("mov.b64 %0, {%1, %2};" : "=l"(r) : "f"(lo), "f"(hi));
    return r;
}
__device__ __forceinline__ unsigned long long ffma2(unsigned long long a,
                                                    unsigned long long b,
                                                    unsigned long long c) {
    unsigned long long d;
    asm("fma.rn.f32x2 %0, %1, %2, %3;" : "=l"(d) : "l"(a), "l"(b), "l"(c));
    return d;
}
__device__ __forceinline__ float2 upk(unsigned long long v) {
    float2 f;
    asm("mov.b64 {%0, %1}, %2;" : "=f"(f.x), "=f"(f.y) : "l"(v));
    return f;
}
// bf16x2 word -> packed f32x2 (lo element in low lane). bf16->f32 is shift<<16.
__device__ __forceinline__ unsigned long long b2f(unsigned int w) {
    unsigned long long r;
    asm("mov.b64 %0, {%1, %2};" : "=l"(r) : "r"(w << 16), "r"(w & 0xffff0000u));
    return r;
}

__global__ __launch_bounds__(NTHREADS, 1)
void sinkhorn_kernel(const float* __restrict__ cost,
                     const float* __restrict__ mass_pred,
                     const float* __restrict__ mass_target) {
    extern __shared__ char smem_raw[];
    __nv_bfloat16* Ks = reinterpret_cast<__nv_bfloat16*>(smem_raw);
    float* part = reinterpret_cast<float*>(smem_raw + PART_OFF);
    float* u_s  = part + PART_FLOATS;     // 256
    float* v_s  = u_s + 256;              // 256
    float* a_s  = v_s + 256;              // 256
    float* b_s  = a_s + 256;              // 256
    float* z2   = b_s + 256;              // 512
    float* red  = z2 + 512;               // 32 scratch

    const int b   = blockIdx.x;
    const int tid = threadIdx.x;
    const float* C = cost + (size_t)b * (NDIM * NDIM);

    // ---- normalize masses ----
    if (tid < 256) {
        a_s[tid] = mass_pred[b * 256 + tid];
        b_s[tid] = mass_target[b * 256 + tid];
    }
    __syncthreads();
    if (tid < 256) {
        float va = a_s[tid], vb = b_s[tid];
        #pragma unroll
        for (int o = 16; o; o >>= 1) {
            va += __shfl_down_sync(0xffffffffu, va, o);
            vb += __shfl_down_sync(0xffffffffu, vb, o);
        }
        if ((tid & 31) == 0) { red[tid >> 5] = va; red[8 + (tid >> 5)] = vb; }
    }
    __syncthreads();
    if (tid == 0) {
        float sa = 0.f, sb = 0.f;
        #pragma unroll
        for (int i = 0; i < 8; i++) { sa += red[i]; sb += red[8 + i]; }
        red[16] = 1.0f / (sa + 1e-8f);
        red[17] = 1.0f / (sb + 1e-8f);
    }
    __syncthreads();
    {
        float inva = red[16], invb = red[17];
        if (tid < 256) {
            a_s[tid] *= inva;
            b_s[tid] *= invb;
            u_s[tid] = 1.0f;
        }
    }

    // ---- build K = exp(-C/eps) in bf16 SMEM (padded rows) ----
    #pragma unroll 4
    for (int j = 0; j < 32; j++) {
        int e = (tid + NTHREADS * j) << 2;              // element index (x4)
        float4 c4 = *reinterpret_cast<const float4*>(C + e);
        int row = e >> 8, col = e & 255;
        __nv_bfloat162 p0 = __floats2bfloat162_rn(__expf(-10.0f * c4.x),
                                                  __expf(-10.0f * c4.y));
        __nv_bfloat162 p1 = __floats2bfloat162_rn(__expf(-10.0f * c4.z),
                                                  __expf(-10.0f * c4.w));
        *reinterpret_cast<__nv_bfloat162*>(&Ks[row * ROWPAD + col])     = p0;
        *reinterpret_cast<__nv_bfloat162*>(&Ks[row * ROWPAD + col + 2]) = p1;
    }
    __syncthreads();

    const int w = tid >> 5, l = tid & 31;

    // ---- 100 Sinkhorn iterations ----
    for (int it = 0; it < ITERS; ++it) {
        // Phase A: y = K^T u  (warp w covers rows [16w,16w+16), lane l cols [8l,8l+8))
        unsigned long long acc0 = 0ull, acc1 = 0ull, acc2 = 0ull, acc3 = 0ull;
        #pragma unroll
        for (int r = 0; r < 16; r++) {
            int n = (w << 4) + r;
            float un = u_s[n];
            unsigned long long u2 = pk2(un, un);
            uint4 kk = *reinterpret_cast<const uint4*>(&Ks[n * ROWPAD + (l << 3)]);
            acc0 = ffma2(b2f(kk.x), u2, acc0);
            acc1 = ffma2(b2f(kk.y), u2, acc1);
            acc2 = ffma2(b2f(kk.z), u2, acc2);
            acc3 = ffma2(b2f(kk.w), u2, acc3);
        }
        {
            float* pp = part + (w << 8) + (l << 3);
            *reinterpret_cast<float2*>(pp)     = upk(acc0);
            *reinterpret_cast<float2*>(pp + 2) = upk(acc1);
            *reinterpret_cast<float2*>(pp + 4) = upk(acc2);
            *reinterpret_cast<float2*>(pp + 6) = upk(acc3);
        }
        __syncthreads();
        if (tid < 256) {
            float s = 0.f;
            #pragma unroll
            for (int q = 0; q < 16; q++) s += part[(q << 8) + tid];
            v_s[tid] = b_s[tid] / (s + 1e-8f);
        }
        __syncthreads();

        // Phase B: z = K v  (thread pair (row, row+256) splits the 32 vec8 chunks)
        {
            int row = tid & 255, h = tid >> 8;
            const uint4* krow = reinterpret_cast<const uint4*>(&Ks[row * ROWPAD]);
            unsigned long long zc0 = 0ull, zc1 = 0ull, zc2 = 0ull, zc3 = 0ull;
            #pragma unroll 4
            for (int c = 0; c < 16; c++) {
                int i = (h << 4) + c;
                uint4 kk = krow[i];
                float4 va = *reinterpret_cast<const float4*>(v_s + (i << 3));
                float4 vb = *reinterpret_cast<const float4*>(v_s + (i << 3) + 4);
                zc0 = ffma2(b2f(kk.x), pk2(va.x, va.y), zc0);
                zc1 = ffma2(b2f(kk.y), pk2(va.z, va.w), zc1);
                zc2 = ffma2(b2f(kk.z), pk2(vb.x, vb.y), zc2);
                zc3 = ffma2(b2f(kk.w), pk2(vb.z, vb.w), zc3);
            }
            float2 f0 = upk(zc0), f1 = upk(zc1), f2 = upk(zc2), f3 = upk(zc3);
            z2[tid] = ((f0.x + f0.y) + (f1.x + f1.y)) +
                      ((f2.x + f2.y) + (f3.x + f3.y));
        }
        __syncthreads();
        if (tid < 256)
            u_s[tid] = a_s[tid] / ((z2[tid] + z2[tid + 256]) + 1e-8f);
        __syncthreads();
    }

    // ---- epilogue: cost_b = sum_nm u[n] * K[n][m] * v[m] * C[n][m] ----
    float partial = 0.f;
    #pragma unroll 4
    for (int j = 0; j < 32; j++) {
        int e = (tid + NTHREADS * j) << 2;
        float4 c4 = *reinterpret_cast<const float4*>(C + e);
        int row = e >> 8, col = e & 255;
        uint2 kk = *reinterpret_cast<const uint2*>(&Ks[row * ROWPAD + col]);
        float un = u_s[row];
        float k0 = __uint_as_float(kk.x << 16);
        float k1 = __uint_as_float(kk.x & 0xffff0000u);
        float k2 = __uint_as_float(kk.y << 16);
        float k3 = __uint_as_float(kk.y & 0xffff0000u);
        partial += un * (v_s[col]     * k0 * c4.x +
                         v_s[col + 1] * k1 * c4.y +
                         v_s[col + 2] * k2 * c4.z +
                         v_s[col + 3] * k3 * c4.w);
    }
    #pragma unroll
    for (int o = 16; o; o >>= 1)
        partial += __shfl_down_sync(0xffffffffu, partial, o);
    if ((tid & 31) == 0) red[tid >> 5] = partial;
    __syncthreads();
    if (tid == 0) {
        float tot = 0.f;
        #pragma unroll
        for (int i = 0; i < 16; i++) tot += red[i];
        g_cost[b] = tot;
    }
}

__global__ void reduce_kernel(float* __restrict__ out) {
    __shared__ float sh[8];
    int t = threadIdx.x;  // 256 threads
    float s = g_cost[t] + g_cost[t + 256] + g_cost[t + 512] + g_cost[t + 768];
    #pragma unroll
    for (int o = 16; o; o >>= 1) s += __shfl_down_sync(0xffffffffu, s, o);
    if ((t & 31) == 0) sh[t >> 5] = s;
    __syncthreads();
    if (t == 0) {
        float tot = 0.f;
        #pragma unroll
        for (int i = 0; i < 8; i++) tot += sh[i];
        out[0] = tot * (1.0f / 1024.0f);
    }
}

extern "C" void kernel_launch(void* const* d_in, const int* in_sizes, int n_in,
                              void* d_out, int out_size) {
    (void)in_sizes; (void)n_in; (void)out_size;
    const float* cost = (const float*)d_in[0];
    const float* mp   = (const float*)d_in[1];
    const float* mt   = (const float*)d_in[2];
    float* out = (float*)d_out;

    cudaFuncSetAttribute(sinkhorn_kernel,
                         cudaFuncAttributeMaxDynamicSharedMemorySize, SMEM_BYTES);
    sinkhorn_kernel<<<BATCH, NTHREADS, SMEM_BYTES>>>(cost, mp, mt);
    reduce_kernel<<<1, 256>>>(out);
}

// round 3
// speedup vs baseline: 1.4031x; 1.4031x over previous
#include <cuda_runtime.h>
#include <cuda_bf16.h>
#include <cstdint>

// Sinkhorn OT: B=1024, N=M=256, 100 iters.
// HMMA (mma.sync m16n8k16 bf16) version — no tcgen05 (not available at .target sm_103).
// One CTA per batch, 512 threads = 16 warps.
//   K bf16 in SMEM (padded 528B rows) + register-resident A-fragments.
//   Phase A (y=K^T u): ldmatrix.x4.trans + mma, u broadcast into B operand.
//   Phase B (z=K v):   register A-frags + mma, v broadcast into B operand.
// No cross-warp reductions; 2 __syncthreads per iteration.

#define BATCH 1024
#define ITERS 100
#define NT    512
#define ROWP  264                       // halves per row (528 B stride)

#define KS_BYTES (256 * ROWP * 2)       // 135168
#define UBF_OFF  KS_BYTES               // 256 bf16
#define VBF_OFF  (UBF_OFF + 512)
#define F32_OFF  (VBF_OFF + 512)        // u_s,v_s,a_s,b_s (256 f32 each) + red
#define SMEM_BYTES (F32_OFF + 4 * 1024 + 128)

__device__ float g_cost[BATCH];

__device__ __forceinline__ uint32_t smem_u32(const void* p) {
    uint32_t a;
    asm("{ .reg .u64 t; cvta.to.shared.u64 t, %1; cvt.u32.u64 %0, t; }" : "=r"(a) : "l"(p));
    return a;
}
__device__ __forceinline__ void ldsm4(uint32_t& f0, uint32_t& f1, uint32_t& f2,
                                      uint32_t& f3, uint32_t addr) {
    asm volatile("ldmatrix.sync.aligned.m8n8.x4.shared.b16 {%0,%1,%2,%3}, [%4];"
                 : "=r"(f0), "=r"(f1), "=r"(f2), "=r"(f3) : "r"(addr));
}
__device__ __forceinline__ void ldsm4t(uint32_t& f0, uint32_t& f1, uint32_t& f2,
                                       uint32_t& f3, uint32_t addr) {
    asm volatile("ldmatrix.sync.aligned.m8n8.x4.trans.shared.b16 {%0,%1,%2,%3}, [%4];"
                 : "=r"(f0), "=r"(f1), "=r"(f2), "=r"(f3) : "r"(addr));
}
__device__ __forceinline__ void mma16816(float& c0, float& c1, float& c2, float& c3,
                                         uint32_t a0, uint32_t a1, uint32_t a2, uint32_t a3,
                                         uint32_t b0, uint32_t b1) {
    asm volatile("mma.sync.aligned.m16n8k16.row.col.f32.bf16.bf16.f32 "
                 "{%0,%1,%2,%3}, {%4,%5,%6,%7}, {%8,%9}, {%0,%1,%2,%3};"
                 : "+f"(c0), "+f"(c1), "+f"(c2), "+f"(c3)
                 : "r"(a0), "r"(a1), "r"(a2), "r"(a3), "r"(b0), "r"(b1));
}
__device__ __forceinline__ uint32_t lds32(uint32_t addr) {
    uint32_t v;
    asm volatile("ld.shared.b32 %0, [%1];" : "=r"(v) : "r"(addr));
    return v;
}
__device__ __forceinline__ void sts16(uint32_t addr, uint16_t v) {
    asm volatile("st.shared.u16 [%0], %1;" :: "r"(addr), "h"(v) : "memory");
}
__device__ __forceinline__ uint16_t f2bf(float f) {
    __nv_bfloat16 h = __float2bfloat16(f);
    return *reinterpret_cast<uint16_t*>(&h);
}

__global__ __launch_bounds__(NT, 1)
void sinkhorn_hmma(const float* __restrict__ cost,
                   const float* __restrict__ mp,
                   const float* __restrict__ mt) {
    extern __shared__ char sm[];
    __nv_bfloat16* Ks = reinterpret_cast<__nv_bfloat16*>(sm);
    float* u_s = reinterpret_cast<float*>(sm + F32_OFF);
    float* v_s = u_s + 256;
    float* a_s = v_s + 256;
    float* b_s = a_s + 256;
    float* red = b_s + 256;     // 32 floats

    const int b   = blockIdx.x;
    const int tid = threadIdx.x;
    const int w   = tid >> 5, lane = tid & 31;
    const int g   = lane >> 2, q = lane & 3;
    const int s   = lane >> 3, r = lane & 7;
    const int m0  = w << 4;
    const float* C = cost + (size_t)b * 65536;

    const uint32_t sb    = smem_u32(sm);
    const uint32_t ubf_b = sb + UBF_OFF;
    const uint32_t vbf_b = sb + VBF_OFF;
    const uint32_t qoff  = (uint32_t)(q << 2);
    // ldmatrix lane base addresses (bytes): K row stride = 528
    const uint32_t taddr = sb + (uint32_t)((r + ((s >> 1) << 3)) * 528 + (m0 + ((s & 1) << 3)) * 2);
    const uint32_t aaddr = sb + (uint32_t)((m0 + r + ((s & 1) << 3)) * 528 + ((s >> 1) << 4));

    // ---- normalize masses ----
    if (tid < 256) {
        a_s[tid] = mp[b * 256 + tid];
        b_s[tid] = mt[b * 256 + tid];
    }
    __syncthreads();
    if (tid < 256) {
        float va = a_s[tid], vb = b_s[tid];
        #pragma unroll
        for (int o = 16; o; o >>= 1) {
            va += __shfl_down_sync(0xffffffffu, va, o);
            vb += __shfl_down_sync(0xffffffffu, vb, o);
        }
        if (lane == 0) { red[w] = va; red[8 + w] = vb; }
    }
    __syncthreads();
    if (tid == 0) {
        float sa = 0.f, sbv = 0.f;
        #pragma unroll
        for (int i = 0; i < 8; i++) { sa += red[i]; sbv += red[8 + i]; }
        red[16] = 1.0f / (sa + 1e-8f);
        red[17] = 1.0f / (sbv + 1e-8f);
    }
    __syncthreads();
    {
        float inva = red[16], invb = red[17];
        if (tid < 256) {
            a_s[tid] *= inva;
            b_s[tid] *= invb;
            u_s[tid] = 1.0f;
            reinterpret_cast<__nv_bfloat16*>(sm + UBF_OFF)[tid] = __float2bfloat16(1.0f);
        }
    }

    // ---- build K = exp(-C/eps) bf16 into padded SMEM rows ----
    #pragma unroll 4
    for (int j = 0; j < 32; j++) {
        int e = (tid + NT * j) << 2;
        float4 c4 = *reinterpret_cast<const float4*>(C + e);
        int row = e >> 8, col = e & 255;
        __nv_bfloat162 p0 = __floats2bfloat162_rn(__expf(-10.0f * c4.x), __expf(-10.0f * c4.y));
        __nv_bfloat162 p1 = __floats2bfloat162_rn(__expf(-10.0f * c4.z), __expf(-10.0f * c4.w));
        *reinterpret_cast<__nv_bfloat162*>(&Ks[row * ROWP + col])     = p0;
        *reinterpret_cast<__nv_bfloat162*>(&Ks[row * ROWP + col + 2]) = p1;
    }
    __syncthreads();

    // ---- prologue: register-resident A-fragments of K rows [m0, m0+16) ----
    uint32_t areg[64];
    #pragma unroll
    for (int j = 0; j < 16; j++)
        ldsm4(areg[4 * j], areg[4 * j + 1], areg[4 * j + 2], areg[4 * j + 3],
              aaddr + (uint32_t)(j << 5));            // +32 B per 16-col chunk

    // ---- 100 Sinkhorn iterations ----
    for (int it = 0; it < ITERS; ++it) {
        // Phase A: y = K^T u  (A = K^T frags via ldmatrix.trans, B = u broadcast)
        float c0 = 0.f, c1 = 0.f, c2 = 0.f, c3 = 0.f;
        #pragma unroll
        for (int j = 0; j < 16; j++) {
            uint32_t f0, f1, f2, f3;
            ldsm4t(f0, f1, f2, f3, taddr + (uint32_t)(j * 8448));   // +16 rows * 528 B
            uint32_t b0 = lds32(ubf_b + (uint32_t)(j << 5) + qoff);
            uint32_t b1 = lds32(ubf_b + (uint32_t)(j << 5) + 16u + qoff);
            mma16816(c0, c1, c2, c3, f0, f1, f2, f3, b0, b1);
        }
        if (q == 0) {          // c0 = y[m0+g], c2 = y[m0+8+g]
            float v0 = b_s[m0 + g]     / (c0 + 1e-8f);
            float v1 = b_s[m0 + 8 + g] / (c2 + 1e-8f);
            v_s[m0 + g] = v0; v_s[m0 + 8 + g] = v1;
            sts16(vbf_b + (uint32_t)((m0 + g) << 1),     f2bf(v0));
            sts16(vbf_b + (uint32_t)((m0 + 8 + g) << 1), f2bf(v1));
        }
        __syncthreads();

        // Phase B: z = K v  (A = register K frags, B = v broadcast)
        c0 = 0.f; c1 = 0.f; c2 = 0.f; c3 = 0.f;
        #pragma unroll
        for (int j = 0; j < 16; j++) {
            uint32_t b0 = lds32(vbf_b + (uint32_t)(j << 5) + qoff);
            uint32_t b1 = lds32(vbf_b + (uint32_t)(j << 5) + 16u + qoff);
            mma16816(c0, c1, c2, c3,
                     areg[4 * j], areg[4 * j + 1], areg[4 * j + 2], areg[4 * j + 3],
                     b0, b1);
        }
        if (q == 0) {          // c0 = z[m0+g], c2 = z[m0+8+g]
            float u0 = a_s[m0 + g]     / (c0 + 1e-8f);
            float u1 = a_s[m0 + 8 + g] / (c2 + 1e-8f);
            u_s[m0 + g] = u0; u_s[m0 + 8 + g] = u1;
            sts16(ubf_b + (uint32_t)((m0 + g) << 1),     f2bf(u0));
            sts16(ubf_b + (uint32_t)((m0 + 8 + g) << 1), f2bf(u1));
        }
        __syncthreads();
    }

    // ---- epilogue: cost_b = sum u[n] K[n][m] v[m] C[n][m] ----
    float part = 0.f;
    #pragma unroll 4
    for (int j = 0; j < 32; j++) {
        int e = (tid + NT * j) << 2;
        int row = e >> 8, col = e & 255;
        float4 c4 = *reinterpret_cast<const float4*>(C + e);
        uint2 kk = *reinterpret_cast<const uint2*>(&Ks[row * ROWP + col]);
        float k0 = __uint_as_float(kk.x << 16);
        float k1 = __uint_as_float(kk.x & 0xffff0000u);
        float k2 = __uint_as_float(kk.y << 16);
        float k3 = __uint_as_float(kk.y & 0xffff0000u);
        float4 v4 = *reinterpret_cast<const float4*>(v_s + col);
        part += u_s[row] * (v4.x * k0 * c4.x + v4.y * k1 * c4.y +
                            v4.z * k2 * c4.z + v4.w * k3 * c4.w);
    }
    #pragma unroll
    for (int o = 16; o; o >>= 1)
        part += __shfl_down_sync(0xffffffffu, part, o);
    if (lane == 0) red[w] = part;
    __syncthreads();
    if (tid == 0) {
        float tot = 0.f;
        #pragma unroll
        for (int i = 0; i < 16; i++) tot += red[i];
        g_cost[b] = tot;
    }
}

__global__ void reduce_kernel(float* __restrict__ out) {
    __shared__ float sh[8];
    int t = threadIdx.x;  // 256
    float s = g_cost[t] + g_cost[t + 256] + g_cost[t + 512] + g_cost[t + 768];
    #pragma unroll
    for (int o = 16; o; o >>= 1) s += __shfl_down_sync(0xffffffffu, s, o);
    if ((t & 31) == 0) sh[t >> 5] = s;
    __syncthreads();
    if (t == 0) {
        float tot = 0.f;
        #pragma unroll
        for (int i = 0; i < 8; i++) tot += sh[i];
        out[0] = tot * (1.0f / 1024.0f);
    }
}

extern "C" void kernel_launch(void* const* d_in, const int* in_sizes, int n_in,
                              void* d_out, int out_size) {
    (void)in_sizes; (void)n_in; (void)out_size;
    const float* cost = (const float*)d_in[0];
    const float* mp   = (const float*)d_in[1];
    const float* mt   = (const float*)d_in[2];
    float* out = (float*)d_out;

    cudaFuncSetAttribute(sinkhorn_hmma,
                         cudaFuncAttributeMaxDynamicSharedMemorySize, SMEM_BYTES);
    sinkhorn_hmma<<<BATCH, NT, SMEM_BYTES>>>(cost, mp, mt);
    reduce_kernel<<<1, 256>>>(out);
}

// round 5
// speedup vs baseline: 1.7937x; 1.2784x over previous
#include <cuda_runtime.h>
#include <cuda_bf16.h>
#include <cstdint>

// Sinkhorn OT: B=1024, N=M=256, 100 iters. HMMA m16n8k16 bf16.
// One CTA per batch, 256 threads = 8 warps, 32 rows per warp (2 m16-tiles).
//  - K fragments (phase B)        : fully register-resident (128 regs)
//  - K^T fragments chunks 0..7    : register-resident (64 regs)
//  - K^T fragments chunks 8..15   : ldmatrix.trans per iter (512 wf/iter)
//  - B-operands: u/v bf16 stored frag-permuted -> one LDS64 per chunk.
// (Resubmission of R4 — previous bench failed with cudaErrorSystemNotReady
//  before any kernel code ran.)

#define BATCH 1024
#define ITERS 100
#define NT    256
#define ROWP  264                       // halves per row (528 B stride)

#define KS_BYTES (256 * ROWP * 2)       // 135168
#define UBF_OFF  KS_BYTES               // 256 bf16 (frag-permuted)
#define VBF_OFF  (UBF_OFF + 512)
#define F32_OFF  (VBF_OFF + 512)        // u_s,v_s,a_s,b_s (256 f32 each) + red
#define SMEM_BYTES (F32_OFF + 4 * 1024 + 128)

__device__ float g_cost[BATCH];

__device__ __forceinline__ uint32_t smem_u32(const void* p) {
    uint32_t a;
    asm("{ .reg .u64 t; cvta.to.shared.u64 t, %1; cvt.u32.u64 %0, t; }" : "=r"(a) : "l"(p));
    return a;
}
__device__ __forceinline__ void ldsm4(uint32_t& f0, uint32_t& f1, uint32_t& f2,
                                      uint32_t& f3, uint32_t addr) {
    asm volatile("ldmatrix.sync.aligned.m8n8.x4.shared.b16 {%0,%1,%2,%3}, [%4];"
                 : "=r"(f0), "=r"(f1), "=r"(f2), "=r"(f3) : "r"(addr));
}
__device__ __forceinline__ void ldsm4t(uint32_t& f0, uint32_t& f1, uint32_t& f2,
                                       uint32_t& f3, uint32_t addr) {
    asm volatile("ldmatrix.sync.aligned.m8n8.x4.trans.shared.b16 {%0,%1,%2,%3}, [%4];"
                 : "=r"(f0), "=r"(f1), "=r"(f2), "=r"(f3) : "r"(addr));
}
__device__ __forceinline__ void mma16816(float& c0, float& c1, float& c2, float& c3,
                                         uint32_t a0, uint32_t a1, uint32_t a2, uint32_t a3,
                                         uint32_t b0, uint32_t b1) {
    asm volatile("mma.sync.aligned.m16n8k16.row.col.f32.bf16.bf16.f32 "
                 "{%0,%1,%2,%3}, {%4,%5,%6,%7}, {%8,%9}, {%0,%1,%2,%3};"
                 : "+f"(c0), "+f"(c1), "+f"(c2), "+f"(c3)
                 : "r"(a0), "r"(a1), "r"(a2), "r"(a3), "r"(b0), "r"(b1));
}
__device__ __forceinline__ uint2 lds64(uint32_t addr) {
    uint2 v;
    asm volatile("ld.shared.v2.b32 {%0,%1}, [%2];" : "=r"(v.x), "=r"(v.y) : "r"(addr));
    return v;
}
__device__ __forceinline__ void sts16(uint32_t addr, uint16_t v) {
    asm volatile("st.shared.u16 [%0], %1;" :: "r"(addr), "h"(v) : "memory");
}
__device__ __forceinline__ uint16_t f2bf(float f) {
    __nv_bfloat16 h = __float2bfloat16(f);
    return *reinterpret_cast<uint16_t*>(&h);
}
// frag-permuted byte offset of vector element rr (bf16):
// chunk j=rr>>4 at j*32; within chunk: q-slot, hi/lo 8-group, parity
__device__ __forceinline__ uint32_t poff(int rr) {
    return (uint32_t)(((rr >> 4) << 5) + (((rr & 7) >> 1) << 3) +
                      (((rr >> 3) & 1) << 2) + ((rr & 1) << 1));
}

__global__ __launch_bounds__(NT, 1)
void sinkhorn_hmma(const float* __restrict__ cost,
                   const float* __restrict__ mp,
                   const float* __restrict__ mt) {
    extern __shared__ char sm[];
    __nv_bfloat16* Ks = reinterpret_cast<__nv_bfloat16*>(sm);
    float* u_s = reinterpret_cast<float*>(sm + F32_OFF);
    float* v_s = u_s + 256;
    float* a_s = v_s + 256;
    float* b_s = a_s + 256;
    float* red = b_s + 256;     // 32 floats

    const int b    = blockIdx.x;
    const int tid  = threadIdx.x;
    const int w    = tid >> 5, lane = tid & 31;
    const int g    = lane >> 2, q = lane & 3;
    const int s    = lane >> 3, r = lane & 7;
    const int row0 = w << 5;                    // 32 rows per warp
    const float* C = cost + (size_t)b * 65536;

    const uint32_t sb    = smem_u32(sm);
    const uint32_t ubf_b = sb + UBF_OFF;
    const uint32_t vbf_b = sb + VBF_OFF;
    const uint32_t qoff8 = (uint32_t)(q << 3);
    // ldmatrix lane base addresses (bytes), verified in R3:
    // A (K rows, row-major):  tiles at m0 = row0, row0+16
    const uint32_t aaddr0 = sb + (uint32_t)((row0 + r + ((s & 1) << 3)) * 528 + ((s >> 1) << 4));
    const uint32_t aaddr1 = aaddr0 + 16u * 528u;
    // A^T (K cols, via .trans): tiles at c0 = row0, row0+16; chunk j adds 16*528
    const uint32_t taddr0 = sb + (uint32_t)((r + ((s >> 1) << 3)) * 528 + (row0 + ((s & 1) << 3)) * 2);
    const uint32_t taddr1 = taddr0 + 32u;

    // ---- normalize masses (256 threads, 1 elem each) ----
    float av = mp[b * 256 + tid];
    float bv = mt[b * 256 + tid];
    {
        float sa = av, sbv = bv;
        #pragma unroll
        for (int o = 16; o; o >>= 1) {
            sa  += __shfl_down_sync(0xffffffffu, sa, o);
            sbv += __shfl_down_sync(0xffffffffu, sbv, o);
        }
        if (lane == 0) { red[w] = sa; red[8 + w] = sbv; }
    }
    __syncthreads();
    if (tid == 0) {
        float sa = 0.f, sbv = 0.f;
        #pragma unroll
        for (int i = 0; i < 8; i++) { sa += red[i]; sbv += red[8 + i]; }
        red[16] = 1.0f / (sa + 1e-8f);
        red[17] = 1.0f / (sbv + 1e-8f);
    }
    // ---- build K = exp(-C/eps) bf16 into padded SMEM rows ----
    #pragma unroll 4
    for (int j = 0; j < 64; j++) {
        int e = (tid + NT * j) << 2;
        float4 c4 = *reinterpret_cast<const float4*>(C + e);
        int row = e >> 8, col = e & 255;
        __nv_bfloat162 p0 = __floats2bfloat162_rn(__expf(-10.0f * c4.x), __expf(-10.0f * c4.y));
        __nv_bfloat162 p1 = __floats2bfloat162_rn(__expf(-10.0f * c4.z), __expf(-10.0f * c4.w));
        *reinterpret_cast<__nv_bfloat162*>(&Ks[row * ROWP + col])     = p0;
        *reinterpret_cast<__nv_bfloat162*>(&Ks[row * ROWP + col + 2]) = p1;
    }
    __syncthreads();
    {
        a_s[tid] = av * red[16];
        b_s[tid] = bv * red[17];
        u_s[tid] = 1.0f;
        if (tid < 128)
            reinterpret_cast<uint32_t*>(sm + UBF_OFF)[tid] = 0x3F803F80u;  // u0 = 1.0
    }

    // ---- prologue: register fragments ----
    uint32_t areg[128];     // K rows [row0, row0+32): 2 tiles x 16 chunks x 4
    #pragma unroll
    for (int j = 0; j < 16; j++) {
        ldsm4(areg[4*j],     areg[4*j+1],     areg[4*j+2],     areg[4*j+3],
              aaddr0 + (uint32_t)(j << 5));
        ldsm4(areg[64+4*j],  areg[64+4*j+1],  areg[64+4*j+2],  areg[64+4*j+3],
              aaddr1 + (uint32_t)(j << 5));
    }
    uint32_t treg[64];      // K^T tiles, chunks 0..7 only: 2 x 8 x 4
    #pragma unroll
    for (int j = 0; j < 8; j++) {
        ldsm4t(treg[4*j],    treg[4*j+1],    treg[4*j+2],    treg[4*j+3],
               taddr0 + (uint32_t)(j * 8448));
        ldsm4t(treg[32+4*j], treg[32+4*j+1], treg[32+4*j+2], treg[32+4*j+3],
               taddr1 + (uint32_t)(j * 8448));
    }
    __syncthreads();

    // ---- 100 Sinkhorn iterations ----
    for (int it = 0; it < ITERS; ++it) {
        // Phase A: y = K^T u   (tile0: y[row0..+16), tile1: y[row0+16..+32))
        {
            float c0 = 0.f, c1 = 0.f, c2 = 0.f, c3 = 0.f;   // tile0
            float d0 = 0.f, d1 = 0.f, d2 = 0.f, d3 = 0.f;   // tile1
            #pragma unroll
            for (int j = 0; j < 8; j++) {
                uint2 bb = lds64(ubf_b + (uint32_t)(j << 5) + qoff8);
                mma16816(c0, c1, c2, c3, treg[4*j], treg[4*j+1], treg[4*j+2], treg[4*j+3], bb.x, bb.y);
                mma16816(d0, d1, d2, d3, treg[32+4*j], treg[32+4*j+1], treg[32+4*j+2], treg[32+4*j+3], bb.x, bb.y);
            }
            #pragma unroll
            for (int j = 8; j < 16; j++) {
                uint2 bb = lds64(ubf_b + (uint32_t)(j << 5) + qoff8);
                uint32_t f0, f1, f2, f3;
                ldsm4t(f0, f1, f2, f3, taddr0 + (uint32_t)(j * 8448));
                mma16816(c0, c1, c2, c3, f0, f1, f2, f3, bb.x, bb.y);
                ldsm4t(f0, f1, f2, f3, taddr1 + (uint32_t)(j * 8448));
                mma16816(d0, d1, d2, d3, f0, f1, f2, f3, bb.x, bb.y);
            }
            // lanes q==0 extract tile0, q==2 extract tile1 (columns are duplicates)
            if (q == 0) {
                int r0 = row0 + g, r1 = row0 + 8 + g;
                float v0 = __fdividef(b_s[r0], c0 + 1e-8f);
                float v1 = __fdividef(b_s[r1], c2 + 1e-8f);
                v_s[r0] = v0; v_s[r1] = v1;
                sts16(vbf_b + poff(r0), f2bf(v0));
                sts16(vbf_b + poff(r1), f2bf(v1));
            } else if (q == 2) {
                int r0 = row0 + 16 + g, r1 = row0 + 24 + g;
                float v0 = __fdividef(b_s[r0], d0 + 1e-8f);
                float v1 = __fdividef(b_s[r1], d2 + 1e-8f);
                v_s[r0] = v0; v_s[r1] = v1;
                sts16(vbf_b + poff(r0), f2bf(v0));
                sts16(vbf_b + poff(r1), f2bf(v1));
            }
        }
        __syncthreads();

        // Phase B: z = K v   (register A-frags, zero SMEM K traffic)
        {
            float c0 = 0.f, c1 = 0.f, c2 = 0.f, c3 = 0.f;
            float d0 = 0.f, d1 = 0.f, d2 = 0.f, d3 = 0.f;
            #pragma unroll
            for (int j = 0; j < 16; j++) {
                uint2 bb = lds64(vbf_b + (uint32_t)(j << 5) + qoff8);
                mma16816(c0, c1, c2, c3, areg[4*j], areg[4*j+1], areg[4*j+2], areg[4*j+3], bb.x, bb.y);
                mma16816(d0, d1, d2, d3, areg[64+4*j], areg[64+4*j+1], areg[64+4*j+2], areg[64+4*j+3], bb.x, bb.y);
            }
            if (q == 0) {
                int r0 = row0 + g, r1 = row0 + 8 + g;
                float u0 = __fdividef(a_s[r0], c0 + 1e-8f);
                float u1 = __fdividef(a_s[r1], c2 + 1e-8f);
                u_s[r0] = u0; u_s[r1] = u1;
                sts16(ubf_b + poff(r0), f2bf(u0));
                sts16(ubf_b + poff(r1), f2bf(u1));
            } else if (q == 2) {
                int r0 = row0 + 16 + g, r1 = row0 + 24 + g;
                float u0 = __fdividef(a_s[r0], d0 + 1e-8f);
                float u1 = __fdividef(a_s[r1], d2 + 1e-8f);
                u_s[r0] = u0; u_s[r1] = u1;
                sts16(ubf_b + poff(r0), f2bf(u0));
                sts16(ubf_b + poff(r1), f2bf(u1));
            }
        }
        __syncthreads();
    }

    // ---- epilogue: cost_b = sum u[n] K[n][m] v[m] C[n][m] ----
    float part = 0.f;
    #pragma unroll 4
    for (int j = 0; j < 64; j++) {
        int e = (tid + NT * j) << 2;
        int row = e >> 8, col = e & 255;
        float4 c4 = *reinterpret_cast<const float4*>(C + e);
        uint2 kk = *reinterpret_cast<const uint2*>(&Ks[row * ROWP + col]);
        float k0 = __uint_as_float(kk.x << 16);
        float k1 = __uint_as_float(kk.x & 0xffff0000u);
        float k2 = __uint_as_float(kk.y << 16);
        float k3 = __uint_as_float(kk.y & 0xffff0000u);
        float4 v4 = *reinterpret_cast<const float4*>(v_s + col);
        part += u_s[row] * (v4.x * k0 * c4.x + v4.y * k1 * c4.y +
                            v4.z * k2 * c4.z + v4.w * k3 * c4.w);
    }
    #pragma unroll
    for (int o = 16; o; o >>= 1)
        part += __shfl_down_sync(0xffffffffu, part, o);
    if (lane == 0) red[w] = part;
    __syncthreads();
    if (tid == 0) {
        float tot = 0.f;
        #pragma unroll
        for (int i = 0; i < 8; i++) tot += red[i];
        g_cost[b] = tot;
    }
}

__global__ void reduce_kernel(float* __restrict__ out) {
    __shared__ float sh[8];
    int t = threadIdx.x;  // 256
    float s = g_cost[t] + g_cost[t + 256] + g_cost[t + 512] + g_cost[t + 768];
    #pragma unroll
    for (int o = 16; o; o >>= 1) s += __shfl_down_sync(0xffffffffu, s, o);
    if ((t & 31) == 0) sh[t >> 5] = s;
    __syncthreads();
    if (t == 0) {
        float tot = 0.f;
        #pragma unroll
        for (int i = 0; i < 8; i++) tot += sh[i];
        out[0] = tot * (1.0f / 1024.0f);
    }
}

extern "C" void kernel_launch(void* const* d_in, const int* in_sizes, int n_in,
                              void* d_out, int out_size) {
    (void)in_sizes; (void)n_in; (void)out_size;
    const float* cost = (const float*)d_in[0];
    const float* mp   = (const float*)d_in[1];
    const float* mt   = (const float*)d_in[2];
    float* out = (float*)d_out;

    cudaFuncSetAttribute(sinkhorn_hmma,
                         cudaFuncAttributeMaxDynamicSharedMemorySize, SMEM_BYTES);
    sinkhorn_hmma<<<BATCH, NT, SMEM_BYTES>>>(cost, mp, mt);
    reduce_kernel<<<1, 256>>>(out);
}

// round 6
// speedup vs baseline: 1.8487x; 1.0306x over previous
#include <cuda_runtime.h>
#include <cuda_bf16.h>
#include <cstdint>

// Sinkhorn OT: B=1024, N=M=256, 100 iters. HMMA m16n8k16 bf16.
// One CTA per batch, 512 threads = 16 warps, 16 rows per warp (1 m16-tile).
//  - K fragments (phase B)     : register-resident (64 regs/thread)
//  - K^T fragments chunks 0..7 : register-resident (32 regs/thread)
//  - K^T fragments chunks 8..15: ldmatrix.trans per iter
//  - B-operands: u/v bf16 frag-permuted -> one LDS64 per chunk
//  - even/odd-chunk accumulator chains for ILP.

#define BATCH 1024
#define ITERS 100
#define NT    512
#define ROWP  264                       // halves per row (528 B stride)

#define KS_BYTES (256 * ROWP * 2)       // 135168
#define UBF_OFF  KS_BYTES               // 256 bf16 (frag-permuted)
#define VBF_OFF  (UBF_OFF + 512)
#define F32_OFF  (VBF_OFF + 512)        // u_s,v_s,a_s,b_s (256 f32 each) + red
#define SMEM_BYTES (F32_OFF + 4 * 1024 + 128)

__device__ float g_cost[BATCH];

__device__ __forceinline__ uint32_t smem_u32(const void* p) {
    uint32_t a;
    asm("{ .reg .u64 t; cvta.to.shared.u64 t, %1; cvt.u32.u64 %0, t; }" : "=r"(a) : "l"(p));
    return a;
}
__device__ __forceinline__ void ldsm4(uint32_t& f0, uint32_t& f1, uint32_t& f2,
                                      uint32_t& f3, uint32_t addr) {
    asm volatile("ldmatrix.sync.aligned.m8n8.x4.shared.b16 {%0,%1,%2,%3}, [%4];"
                 : "=r"(f0), "=r"(f1), "=r"(f2), "=r"(f3) : "r"(addr));
}
__device__ __forceinline__ void ldsm4t(uint32_t& f0, uint32_t& f1, uint32_t& f2,
                                       uint32_t& f3, uint32_t addr) {
    asm volatile("ldmatrix.sync.aligned.m8n8.x4.trans.shared.b16 {%0,%1,%2,%3}, [%4];"
                 : "=r"(f0), "=r"(f1), "=r"(f2), "=r"(f3) : "r"(addr));
}
__device__ __forceinline__ void mma16816(float& c0, float& c1, float& c2, float& c3,
                                         uint32_t a0, uint32_t a1, uint32_t a2, uint32_t a3,
                                         uint32_t b0, uint32_t b1) {
    asm volatile("mma.sync.aligned.m16n8k16.row.col.f32.bf16.bf16.f32 "
                 "{%0,%1,%2,%3}, {%4,%5,%6,%7}, {%8,%9}, {%0,%1,%2,%3};"
                 : "+f"(c0), "+f"(c1), "+f"(c2), "+f"(c3)
                 : "r"(a0), "r"(a1), "r"(a2), "r"(a3), "r"(b0), "r"(b1));
}
__device__ __forceinline__ uint2 lds64(uint32_t addr) {
    uint2 v;
    asm volatile("ld.shared.v2.b32 {%0,%1}, [%2];" : "=r"(v.x), "=r"(v.y) : "r"(addr));
    return v;
}
__device__ __forceinline__ void sts16(uint32_t addr, uint16_t v) {
    asm volatile("st.shared.u16 [%0], %1;" :: "r"(addr), "h"(v) : "memory");
}
__device__ __forceinline__ uint16_t f2bf(float f) {
    __nv_bfloat16 h = __float2bfloat16(f);
    return *reinterpret_cast<uint16_t*>(&h);
}
// frag-permuted byte offset of vector element rr (bf16)
__device__ __forceinline__ uint32_t poff(int rr) {
    return (uint32_t)(((rr >> 4) << 5) + (((rr & 7) >> 1) << 3) +
                      (((rr >> 3) & 1) << 2) + ((rr & 1) << 1));
}

__global__ __launch_bounds__(NT, 1)
void sinkhorn_hmma(const float* __restrict__ cost,
                   const float* __restrict__ mp,
                   const float* __restrict__ mt) {
    extern __shared__ char sm[];
    __nv_bfloat16* Ks = reinterpret_cast<__nv_bfloat16*>(sm);
    float* u_s = reinterpret_cast<float*>(sm + F32_OFF);
    float* v_s = u_s + 256;
    float* a_s = v_s + 256;
    float* b_s = a_s + 256;
    float* red = b_s + 256;     // 32 floats

    const int b    = blockIdx.x;
    const int tid  = threadIdx.x;
    const int w    = tid >> 5, lane = tid & 31;
    const int g    = lane >> 2, q = lane & 3;
    const int s    = lane >> 3, r = lane & 7;
    const int row0 = w << 4;                    // 16 rows per warp
    const float* C = cost + (size_t)b * 65536;

    const uint32_t sb    = smem_u32(sm);
    const uint32_t ubf_b = sb + UBF_OFF;
    const uint32_t vbf_b = sb + VBF_OFF;
    const uint32_t qoff8 = (uint32_t)(q << 3);
    // ldmatrix lane base addresses (verified R3/R5):
    const uint32_t aaddr = sb + (uint32_t)((row0 + r + ((s & 1) << 3)) * 528 + ((s >> 1) << 4));
    const uint32_t taddr = sb + (uint32_t)((r + ((s >> 1) << 3)) * 528 + (row0 + ((s & 1) << 3)) * 2);

    // ---- normalize masses ----
    if (tid < 256) {
        float av = mp[b * 256 + tid];
        float bv = mt[b * 256 + tid];
        a_s[tid] = av; b_s[tid] = bv;
        float sa = av, sbv = bv;
        #pragma unroll
        for (int o = 16; o; o >>= 1) {
            sa  += __shfl_down_sync(0xffffffffu, sa, o);
            sbv += __shfl_down_sync(0xffffffffu, sbv, o);
        }
        if (lane == 0) { red[w] = sa; red[8 + w] = sbv; }
    }
    __syncthreads();
    if (tid == 0) {
        float sa = 0.f, sbv = 0.f;
        #pragma unroll
        for (int i = 0; i < 8; i++) { sa += red[i]; sbv += red[8 + i]; }
        red[16] = 1.0f / (sa + 1e-8f);
        red[17] = 1.0f / (sbv + 1e-8f);
    }
    // ---- build K = exp(-C/eps) bf16 into padded SMEM rows ----
    #pragma unroll 4
    for (int j = 0; j < 32; j++) {
        int e = (tid + NT * j) << 2;
        float4 c4 = *reinterpret_cast<const float4*>(C + e);
        int row = e >> 8, col = e & 255;
        __nv_bfloat162 p0 = __floats2bfloat162_rn(__expf(-10.0f * c4.x), __expf(-10.0f * c4.y));
        __nv_bfloat162 p1 = __floats2bfloat162_rn(__expf(-10.0f * c4.z), __expf(-10.0f * c4.w));
        *reinterpret_cast<__nv_bfloat162*>(&Ks[row * ROWP + col])     = p0;
        *reinterpret_cast<__nv_bfloat162*>(&Ks[row * ROWP + col + 2]) = p1;
    }
    __syncthreads();
    if (tid < 256) {
        a_s[tid] *= red[16];
        b_s[tid] *= red[17];
        u_s[tid] = 1.0f;
        if (tid < 128)
            reinterpret_cast<uint32_t*>(sm + UBF_OFF)[tid] = 0x3F803F80u;  // u0 = 1.0
    }

    // ---- prologue: register fragments ----
    uint32_t areg[64];      // K rows [row0, row0+16): 16 chunks x 4
    #pragma unroll
    for (int j = 0; j < 16; j++)
        ldsm4(areg[4*j], areg[4*j+1], areg[4*j+2], areg[4*j+3],
              aaddr + (uint32_t)(j << 5));
    uint32_t treg[32];      // K^T tile, chunks 0..7: 8 x 4
    #pragma unroll
    for (int j = 0; j < 8; j++)
        ldsm4t(treg[4*j], treg[4*j+1], treg[4*j+2], treg[4*j+3],
               taddr + (uint32_t)(j * 8448));
    __syncthreads();

    // ---- 100 Sinkhorn iterations ----
    for (int it = 0; it < ITERS; ++it) {
        // Phase A: y = K^T u  (even/odd chunk accumulator chains)
        {
            float e0 = 0.f, e1 = 0.f, e2 = 0.f, e3 = 0.f;
            float o0 = 0.f, o1 = 0.f, o2 = 0.f, o3 = 0.f;
            #pragma unroll
            for (int j = 0; j < 8; j += 2) {
                uint2 b0 = lds64(ubf_b + (uint32_t)(j << 5) + qoff8);
                uint2 b1 = lds64(ubf_b + (uint32_t)((j + 1) << 5) + qoff8);
                mma16816(e0, e1, e2, e3, treg[4*j], treg[4*j+1], treg[4*j+2], treg[4*j+3], b0.x, b0.y);
                mma16816(o0, o1, o2, o3, treg[4*j+4], treg[4*j+5], treg[4*j+6], treg[4*j+7], b1.x, b1.y);
            }
            #pragma unroll
            for (int j = 8; j < 16; j += 2) {
                uint2 b0 = lds64(ubf_b + (uint32_t)(j << 5) + qoff8);
                uint2 b1 = lds64(ubf_b + (uint32_t)((j + 1) << 5) + qoff8);
                uint32_t f0, f1, f2, f3, h0, h1, h2, h3;
                ldsm4t(f0, f1, f2, f3, taddr + (uint32_t)(j * 8448));
                ldsm4t(h0, h1, h2, h3, taddr + (uint32_t)((j + 1) * 8448));
                mma16816(e0, e1, e2, e3, f0, f1, f2, f3, b0.x, b0.y);
                mma16816(o0, o1, o2, o3, h0, h1, h2, h3, b1.x, b1.y);
            }
            if (q == 0) {
                int r0 = row0 + g, r1 = row0 + 8 + g;
                float v0 = __fdividef(b_s[r0], (e0 + o0) + 1e-8f);
                float v1 = __fdividef(b_s[r1], (e2 + o2) + 1e-8f);
                v_s[r0] = v0; v_s[r1] = v1;
                sts16(vbf_b + poff(r0), f2bf(v0));
                sts16(vbf_b + poff(r1), f2bf(v1));
            }
        }
        __syncthreads();

        // Phase B: z = K v  (register A-frags only)
        {
            float e0 = 0.f, e1 = 0.f, e2 = 0.f, e3 = 0.f;
            float o0 = 0.f, o1 = 0.f, o2 = 0.f, o3 = 0.f;
            #pragma unroll
            for (int j = 0; j < 16; j += 2) {
                uint2 b0 = lds64(vbf_b + (uint32_t)(j << 5) + qoff8);
                uint2 b1 = lds64(vbf_b + (uint32_t)((j + 1) << 5) + qoff8);
                mma16816(e0, e1, e2, e3, areg[4*j], areg[4*j+1], areg[4*j+2], areg[4*j+3], b0.x, b0.y);
                mma16816(o0, o1, o2, o3, areg[4*j+4], areg[4*j+5], areg[4*j+6], areg[4*j+7], b1.x, b1.y);
            }
            if (q == 0) {
                int r0 = row0 + g, r1 = row0 + 8 + g;
                float u0 = __fdividef(a_s[r0], (e0 + o0) + 1e-8f);
                float u1 = __fdividef(a_s[r1], (e2 + o2) + 1e-8f);
                u_s[r0] = u0; u_s[r1] = u1;
                sts16(ubf_b + poff(r0), f2bf(u0));
                sts16(ubf_b + poff(r1), f2bf(u1));
            }
        }
        __syncthreads();
    }

    // ---- epilogue: cost_b = sum u[n] K[n][m] v[m] C[n][m] ----
    float part = 0.f;
    #pragma unroll 4
    for (int j = 0; j < 32; j++) {
        int e = (tid + NT * j) << 2;
        int row = e >> 8, col = e & 255;
        float4 c4 = *reinterpret_cast<const float4*>(C + e);
        uint2 kk = *reinterpret_cast<const uint2*>(&Ks[row * ROWP + col]);
        float k0 = __uint_as_float(kk.x << 16);
        float k1 = __uint_as_float(kk.x & 0xffff0000u);
        float k2 = __uint_as_float(kk.y << 16);
        float k3 = __uint_as_float(kk.y & 0xffff0000u);
        float4 v4 = *reinterpret_cast<const float4*>(v_s + col);
        part += u_s[row] * (v4.x * k0 * c4.x + v4.y * k1 * c4.y +
                            v4.z * k2 * c4.z + v4.w * k3 * c4.w);
    }
    #pragma unroll
    for (int o = 16; o; o >>= 1)
        part += __shfl_down_sync(0xffffffffu, part, o);
    if (lane == 0) red[w] = part;
    __syncthreads();
    if (tid == 0) {
        float tot = 0.f;
        #pragma unroll
        for (int i = 0; i < 16; i++) tot += red[i];
        g_cost[b] = tot;
    }
}

__global__ void reduce_kernel(float* __restrict__ out) {
    __shared__ float sh[8];
    int t = threadIdx.x;  // 256
    float s = g_cost[t] + g_cost[t + 256] + g_cost[t + 512] + g_cost[t + 768];
    #pragma unroll
    for (int o = 16; o; o >>= 1) s += __shfl_down_sync(0xffffffffu, s, o);
    if ((t & 31) == 0) sh[t >> 5] = s;
    __syncthreads();
    if (t == 0) {
        float tot = 0.f;
        #pragma unroll
        for (int i = 0; i < 8; i++) tot += sh[i];
        out[0] = tot * (1.0f / 1024.0f);
    }
}

extern "C" void kernel_launch(void* const* d_in, const int* in_sizes, int n_in,
                              void* d_out, int out_size) {
    (void)in_sizes; (void)n_in; (void)out_size;
    const float* cost = (const float*)d_in[0];
    const float* mp   = (const float*)d_in[1];
    const float* mt   = (const float*)d_in[2];
    float* out = (float*)d_out;

    cudaFuncSetAttribute(sinkhorn_hmma,
                         cudaFuncAttributeMaxDynamicSharedMemorySize, SMEM_BYTES);
    sinkhorn_hmma<<<BATCH, NT, SMEM_BYTES>>>(cost, mp, mt);
    reduce_kernel<<<1, 256>>>(out);
}

// round 7
// speedup vs baseline: 1.8574x; 1.0047x over previous
#include <cuda_runtime.h>
#include <cuda_fp16.h>
#include <cstdint>

// Sinkhorn OT: B=1024, N=M=256, 100 iters. HMMA m16n8k16 **fp16 end-to-end**
// (fp16 operands + fp16 accumulators — testing 2x-rate f16-accum hypothesis).
// One CTA per batch, 512 threads = 16 warps, 16 rows per warp.
//  - K fragments (phase B)     : register-resident (64 regs/thread)
//  - K^T fragments chunks 0..7 : register-resident (32 regs/thread)
//  - K^T fragments chunks 8..15: ldmatrix.trans per iter
//  - B-operands: u/v f16 frag-permuted -> one LDS64 per chunk
//  - even/odd-chunk accumulator chains; divides in fp32.

#define BATCH 1024
#define ITERS 100
#define NT    512
#define ROWP  264                       // halves per row (528 B stride)

#define KS_BYTES (256 * ROWP * 2)       // 135168
#define UBF_OFF  KS_BYTES               // 256 f16 (frag-permuted)
#define VBF_OFF  (UBF_OFF + 512)
#define F32_OFF  (VBF_OFF + 512)        // u_s,v_s,a_s,b_s (256 f32 each) + red
#define SMEM_BYTES (F32_OFF + 4 * 1024 + 128)

__device__ float g_cost[BATCH];

__device__ __forceinline__ uint32_t smem_u32(const void* p) {
    uint32_t a;
    asm("{ .reg .u64 t; cvta.to.shared.u64 t, %1; cvt.u32.u64 %0, t; }" : "=r"(a) : "l"(p));
    return a;
}
__device__ __forceinline__ void ldsm4(uint32_t& f0, uint32_t& f1, uint32_t& f2,
                                      uint32_t& f3, uint32_t addr) {
    asm volatile("ldmatrix.sync.aligned.m8n8.x4.shared.b16 {%0,%1,%2,%3}, [%4];"
                 : "=r"(f0), "=r"(f1), "=r"(f2), "=r"(f3) : "r"(addr));
}
__device__ __forceinline__ void ldsm4t(uint32_t& f0, uint32_t& f1, uint32_t& f2,
                                       uint32_t& f3, uint32_t addr) {
    asm volatile("ldmatrix.sync.aligned.m8n8.x4.trans.shared.b16 {%0,%1,%2,%3}, [%4];"
                 : "=r"(f0), "=r"(f1), "=r"(f2), "=r"(f3) : "r"(addr));
}
// fp16 operands, fp16 accumulator (2 c-regs)
__device__ __forceinline__ void mma_f16(uint32_t& c0, uint32_t& c1,
                                        uint32_t a0, uint32_t a1, uint32_t a2, uint32_t a3,
                                        uint32_t b0, uint32_t b1) {
    asm volatile("mma.sync.aligned.m16n8k16.row.col.f16.f16.f16.f16 "
                 "{%0,%1}, {%2,%3,%4,%5}, {%6,%7}, {%0,%1};"
                 : "+r"(c0), "+r"(c1)
                 : "r"(a0), "r"(a1), "r"(a2), "r"(a3), "r"(b0), "r"(b1));
}
__device__ __forceinline__ uint2 lds64(uint32_t addr) {
    uint2 v;
    asm volatile("ld.shared.v2.b32 {%0,%1}, [%2];" : "=r"(v.x), "=r"(v.y) : "r"(addr));
    return v;
}
__device__ __forceinline__ void sts16(uint32_t addr, uint16_t v) {
    asm volatile("st.shared.u16 [%0], %1;" :: "r"(addr), "h"(v) : "memory");
}
__device__ __forceinline__ uint16_t f2h(float f) {
    __half h = __float2half_rn(f);
    return *reinterpret_cast<uint16_t*>(&h);
}
__device__ __forceinline__ float lo16(uint32_t w) {
    return __half2float(__ushort_as_half((unsigned short)(w & 0xFFFFu)));
}
__device__ __forceinline__ float hi16(uint32_t w) {
    return __half2float(__ushort_as_half((unsigned short)(w >> 16)));
}
// frag-permuted byte offset of vector element rr (f16)
__device__ __forceinline__ uint32_t poff(int rr) {
    return (uint32_t)(((rr >> 4) << 5) + (((rr & 7) >> 1) << 3) +
                      (((rr >> 3) & 1) << 2) + ((rr & 1) << 1));
}

__global__ __launch_bounds__(NT, 1)
void sinkhorn_hmma(const float* __restrict__ cost,
                   const float* __restrict__ mp,
                   const float* __restrict__ mt) {
    extern __shared__ char sm[];
    __half* Ks = reinterpret_cast<__half*>(sm);
    float* u_s = reinterpret_cast<float*>(sm + F32_OFF);
    float* v_s = u_s + 256;
    float* a_s = v_s + 256;
    float* b_s = a_s + 256;
    float* red = b_s + 256;     // 32 floats

    const int b    = blockIdx.x;
    const int tid  = threadIdx.x;
    const int w    = tid >> 5, lane = tid & 31;
    const int g    = lane >> 2, q = lane & 3;
    const int s    = lane >> 3, r = lane & 7;
    const int row0 = w << 4;                    // 16 rows per warp
    const float* C = cost + (size_t)b * 65536;

    const uint32_t sb    = smem_u32(sm);
    const uint32_t ubf_b = sb + UBF_OFF;
    const uint32_t vbf_b = sb + VBF_OFF;
    const uint32_t qoff8 = (uint32_t)(q << 3);
    // ldmatrix lane base addresses (verified R3/R5/R6):
    const uint32_t aaddr = sb + (uint32_t)((row0 + r + ((s & 1) << 3)) * 528 + ((s >> 1) << 4));
    const uint32_t taddr = sb + (uint32_t)((r + ((s >> 1) << 3)) * 528 + (row0 + ((s & 1) << 3)) * 2);

    // ---- normalize masses ----
    if (tid < 256) {
        float av = mp[b * 256 + tid];
        float bv = mt[b * 256 + tid];
        a_s[tid] = av; b_s[tid] = bv;
        float sa = av, sbv = bv;
        #pragma unroll
        for (int o = 16; o; o >>= 1) {
            sa  += __shfl_down_sync(0xffffffffu, sa, o);
            sbv += __shfl_down_sync(0xffffffffu, sbv, o);
        }
        if (lane == 0) { red[w] = sa; red[8 + w] = sbv; }
    }
    __syncthreads();
    if (tid == 0) {
        float sa = 0.f, sbv = 0.f;
        #pragma unroll
        for (int i = 0; i < 8; i++) { sa += red[i]; sbv += red[8 + i]; }
        red[16] = 1.0f / (sa + 1e-8f);
        red[17] = 1.0f / (sbv + 1e-8f);
    }
    // ---- build K = exp(-C/eps) f16 into padded SMEM rows ----
    #pragma unroll 4
    for (int j = 0; j < 32; j++) {
        int e = (tid + NT * j) << 2;
        float4 c4 = *reinterpret_cast<const float4*>(C + e);
        int row = e >> 8, col = e & 255;
        __half2 p0 = __floats2half2_rn(__expf(-10.0f * c4.x), __expf(-10.0f * c4.y));
        __half2 p1 = __floats2half2_rn(__expf(-10.0f * c4.z), __expf(-10.0f * c4.w));
        *reinterpret_cast<__half2*>(&Ks[row * ROWP + col])     = p0;
        *reinterpret_cast<__half2*>(&Ks[row * ROWP + col + 2]) = p1;
    }
    __syncthreads();
    if (tid < 256) {
        a_s[tid] *= red[16];
        b_s[tid] *= red[17];
        u_s[tid] = 1.0f;
        if (tid < 128)
            reinterpret_cast<uint32_t*>(sm + UBF_OFF)[tid] = 0x3C003C00u;  // u0 = 1.0 (f16)
    }

    // ---- prologue: register fragments ----
    uint32_t areg[64];      // K rows [row0, row0+16): 16 chunks x 4
    #pragma unroll
    for (int j = 0; j < 16; j++)
        ldsm4(areg[4*j], areg[4*j+1], areg[4*j+2], areg[4*j+3],
              aaddr + (uint32_t)(j << 5));
    uint32_t treg[32];      // K^T tile, chunks 0..7: 8 x 4
    #pragma unroll
    for (int j = 0; j < 8; j++)
        ldsm4t(treg[4*j], treg[4*j+1], treg[4*j+2], treg[4*j+3],
               taddr + (uint32_t)(j * 8448));
    __syncthreads();

    // ---- 100 Sinkhorn iterations ----
    for (int it = 0; it < ITERS; ++it) {
        // Phase A: y = K^T u  (even/odd chunk accumulator chains, f16 accum)
        {
            uint32_t ce0 = 0u, ce1 = 0u;     // even chain: rows g / 8+g
            uint32_t co0 = 0u, co1 = 0u;     // odd chain
            #pragma unroll
            for (int j = 0; j < 8; j += 2) {
                uint2 b0 = lds64(ubf_b + (uint32_t)(j << 5) + qoff8);
                uint2 b1 = lds64(ubf_b + (uint32_t)((j + 1) << 5) + qoff8);
                mma_f16(ce0, ce1, treg[4*j], treg[4*j+1], treg[4*j+2], treg[4*j+3], b0.x, b0.y);
                mma_f16(co0, co1, treg[4*j+4], treg[4*j+5], treg[4*j+6], treg[4*j+7], b1.x, b1.y);
            }
            #pragma unroll
            for (int j = 8; j < 16; j += 2) {
                uint2 b0 = lds64(ubf_b + (uint32_t)(j << 5) + qoff8);
                uint2 b1 = lds64(ubf_b + (uint32_t)((j + 1) << 5) + qoff8);
                uint32_t f0, f1, f2, f3, h0, h1, h2, h3;
                ldsm4t(f0, f1, f2, f3, taddr + (uint32_t)(j * 8448));
                ldsm4t(h0, h1, h2, h3, taddr + (uint32_t)((j + 1) * 8448));
                mma_f16(ce0, ce1, f0, f1, f2, f3, b0.x, b0.y);
                mma_f16(co0, co1, h0, h1, h2, h3, b1.x, b1.y);
            }
            if (q == 0) {
                int r0 = row0 + g, r1 = row0 + 8 + g;
                float y0 = lo16(ce0) + lo16(co0);
                float y1 = lo16(ce1) + lo16(co1);
                float v0 = __fdividef(b_s[r0], y0 + 1e-8f);
                float v1 = __fdividef(b_s[r1], y1 + 1e-8f);
                v_s[r0] = v0; v_s[r1] = v1;
                sts16(vbf_b + poff(r0), f2h(v0));
                sts16(vbf_b + poff(r1), f2h(v1));
            }
        }
        __syncthreads();

        // Phase B: z = K v  (register A-frags only)
        {
            uint32_t ce0 = 0u, ce1 = 0u;
            uint32_t co0 = 0u, co1 = 0u;
            #pragma unroll
            for (int j = 0; j < 16; j += 2) {
                uint2 b0 = lds64(vbf_b + (uint32_t)(j << 5) + qoff8);
                uint2 b1 = lds64(vbf_b + (uint32_t)((j + 1) << 5) + qoff8);
                mma_f16(ce0, ce1, areg[4*j], areg[4*j+1], areg[4*j+2], areg[4*j+3], b0.x, b0.y);
                mma_f16(co0, co1, areg[4*j+4], areg[4*j+5], areg[4*j+6], areg[4*j+7], b1.x, b1.y);
            }
            if (q == 0) {
                int r0 = row0 + g, r1 = row0 + 8 + g;
                float z0 = lo16(ce0) + lo16(co0);
                float z1 = lo16(ce1) + lo16(co1);
                float u0 = __fdividef(a_s[r0], z0 + 1e-8f);
                float u1 = __fdividef(a_s[r1], z1 + 1e-8f);
                u_s[r0] = u0; u_s[r1] = u1;
                sts16(ubf_b + poff(r0), f2h(u0));
                sts16(ubf_b + poff(r1), f2h(u1));
            }
        }
        __syncthreads();
    }

    // ---- epilogue: cost_b = sum u[n] K[n][m] v[m] C[n][m] ----
    float part = 0.f;
    #pragma unroll 4
    for (int j = 0; j < 32; j++) {
        int e = (tid + NT * j) << 2;
        int row = e >> 8, col = e & 255;
        float4 c4 = *reinterpret_cast<const float4*>(C + e);
        uint2 kk = *reinterpret_cast<const uint2*>(&Ks[row * ROWP + col]);
        float k0 = lo16(kk.x), k1 = hi16(kk.x);
        float k2 = lo16(kk.y), k3 = hi16(kk.y);
        float4 v4 = *reinterpret_cast<const float4*>(v_s + col);
        part += u_s[row] * (v4.x * k0 * c4.x + v4.y * k1 * c4.y +
                            v4.z * k2 * c4.z + v4.w * k3 * c4.w);
    }
    #pragma unroll
    for (int o = 16; o; o >>= 1)
        part += __shfl_down_sync(0xffffffffu, part, o);
    if (lane == 0) red[w] = part;
    __syncthreads();
    if (tid == 0) {
        float tot = 0.f;
        #pragma unroll
        for (int i = 0; i < 16; i++) tot += red[i];
        g_cost[b] = tot;
    }
}

__global__ void reduce_kernel(float* __restrict__ out) {
    __shared__ float sh[8];
    int t = threadIdx.x;  // 256
    float s = g_cost[t] + g_cost[t + 256] + g_cost[t + 512] + g_cost[t + 768];
    #pragma unroll
    for (int o = 16; o; o >>= 1) s += __shfl_down_sync(0xffffffffu, s, o);
    if ((t & 31) == 0) sh[t >> 5] = s;
    __syncthreads();
    if (t == 0) {
        float tot = 0.f;
        #pragma unroll
        for (int i = 0; i < 8; i++) tot += sh[i];
        out[0] = tot * (1.0f / 1024.0f);
    }
}

extern "C" void kernel_launch(void* const* d_in, const int* in_sizes, int n_in,
                              void* d_out, int out_size) {
    (void)in_sizes; (void)n_in; (void)out_size;
    const float* cost = (const float*)d_in[0];
    const float* mp   = (const float*)d_in[1];
    const float* mt   = (const float*)d_in[2];
    float* out = (float*)d_out;

    cudaFuncSetAttribute(sinkhorn_hmma,
                         cudaFuncAttributeMaxDynamicSharedMemorySize, SMEM_BYTES);
    sinkhorn_hmma<<<BATCH, NT, SMEM_BYTES>>>(cost, mp, mt);
    reduce_kernel<<<1, 256>>>(out);
}